// round 13
// baseline (speedup 1.0000x reference)
#include <cuda_runtime.h>
#include <cuda_fp16.h>
#include <cstdint>

// ===================== problem constants =====================
#define DDIM 256
#define HDIM 256
#define EDIM 5
#define BM   64            // rows per MMA CTA
#define KC   64            // k per smem chunk (4 mma k-steps)
#define NCHUNK (DDIM / KC) // 4
#define TAU  3e-3f
#define FIXCAP 16384
#define RPF  16

// W smem leading dim (fp16), padded for conflict-free ldmatrix
#define WS_LD 264
#define WBUF_BYTES (KC * WS_LD * 2)   // 33792

// dynamic smem byte offsets (MMA kernel) — 3 W buffers + tables
#define WS0_OFF   0
#define WS1_OFF   33792
#define WS2_OFF   67584
#define PLOG_OFF  101376   // float[64][4][5] = 5120
#define B1_OFF    106496   // 1024
#define W2_OFF    107520   // 5120
#define B2_OFF    112640   // 64
#define SMEM_TOTAL 112704

// ===================== device scratch =====================
__device__ int    g_count;
__device__ int    g_rows[FIXCAP];
__device__ __half g_w1h[DDIM * HDIM];

// ===================== PTX helpers =====================
__device__ __forceinline__ uint32_t smem_u32(const void* p) {
    uint32_t a;
    asm("{ .reg .u64 t; cvta.to.shared.u64 t, %1; cvt.u32.u64 %0, t; }" : "=r"(a) : "l"(p));
    return a;
}

#define LDSM_X4_T(r0, r1, r2, r3, addr)                                            \
    asm volatile("ldmatrix.sync.aligned.m8n8.x4.trans.shared.b16 {%0,%1,%2,%3}, [%4];" \
        : "=r"(r0), "=r"(r1), "=r"(r2), "=r"(r3) : "r"(addr))

#define MMA_F16(d, a, b0, b1)                                                      \
    asm volatile("mma.sync.aligned.m16n8k16.row.col.f32.f16.f16.f32 "              \
        "{%0,%1,%2,%3}, {%4,%5,%6,%7}, {%8,%9}, {%0,%1,%2,%3};"                    \
        : "+f"((d)[0]), "+f"((d)[1]), "+f"((d)[2]), "+f"((d)[3])                   \
        : "r"((a)[0]), "r"((a)[1]), "r"((a)[2]), "r"((a)[3]), "r"(b0), "r"(b1))

#define CP_ASYNC16(dst, src)                                                       \
    asm volatile("cp.async.cg.shared.global [%0], [%1], 16;" :: "r"(dst), "l"(src))
#define CP_COMMIT() asm volatile("cp.async.commit_group;" ::: "memory")
#define CP_WAIT(n)  asm volatile("cp.async.wait_group %0;" :: "n"(n) : "memory")

__device__ __forceinline__ uint32_t pack_h2(float a, float b) {
    __half2 v = __floats2half2_rn(a, b);
    return *reinterpret_cast<uint32_t*>(&v);
}

// ===================== kernel 0: prep =====================
__global__ __launch_bounds__(256)
void prep_kernel(const float* __restrict__ W1) {
    int i = blockIdx.x * 256 + threadIdx.x;
    g_w1h[i] = __float2half(W1[i]);
    if (i == 0) g_count = 0;
}

// ===================== kernel 1: MMA kernel, 3-stage pipeline =====================
__global__ __launch_bounds__(256, 1)
void gating_mma_kernel(const float* __restrict__ x,
                       const float* __restrict__ b1,
                       const float* __restrict__ W2,
                       const float* __restrict__ b2,
                       float* __restrict__ out_gates,
                       float* __restrict__ out_idx,
                       int write_idx)
{
    extern __shared__ __align__(128) char smem[];
    const uint32_t sb = smem_u32(smem);
    const int tid  = threadIdx.x;
    const int wrp  = tid >> 5;
    const int ln   = tid & 31;
    const int mw   = wrp >> 2;
    const int nw   = wrp & 3;
    const long long row0 = (long long)blockIdx.x * BM;

    float* plog = (float*)(smem + PLOG_OFF);
    float* b1s  = (float*)(smem + B1_OFF);
    float* w2s  = (float*)(smem + W2_OFF);
    float* b2s  = (float*)(smem + B2_OFF);

    b1s[tid] = b1[tid];
    if (tid < EDIM) b2s[tid] = b2[tid];
    #pragma unroll
    for (int i = 0; i < 5; i++) {
        int v = tid + i * 256;
        if (v < HDIM * EDIM) w2s[v] = W2[v];
    }

    const float2* xg2 = (const float2*)x;
    size_t rb[4];
    #pragma unroll
    for (int i = 0; i < 4; i++)
        rb[i] = (size_t)(row0 + mw * 32 + (ln >> 2) + 8 * i) * DDIM;
    const int cth = (ln & 3) * 2;

    const uint32_t ws_off[3] = {WS0_OFF, WS1_OFF, WS2_OFF};

    auto cp_async_W = [&](int chunk, uint32_t off) {
        const __half* src_base = g_w1h + (size_t)(chunk * KC) * HDIM;
        #pragma unroll
        for (int t = 0; t < 8; t++) {
            int v = tid + t * 256;       // 0..2047
            int r = v >> 5;              // k-row 0..63
            int g = v & 31;              // 16B group
            uint32_t dst = sb + off + (uint32_t)(r * (WS_LD * 2) + g * 16);
            CP_ASYNC16(dst, src_base + r * HDIM + g * 8);
        }
    };

    float c[2][8][4];
    #pragma unroll
    for (int mt = 0; mt < 2; mt++)
        #pragma unroll
        for (int nt = 0; nt < 8; nt++)
            #pragma unroll
            for (int r = 0; r < 4; r++)
                c[mt][nt][r] = 0.0f;

    // prologue: 2 chunks in flight
    cp_async_W(0, ws_off[0]); CP_COMMIT();
    cp_async_W(1, ws_off[1]); CP_COMMIT();

    #pragma unroll
    for (int kc = 0; kc < NCHUNK; kc++) {
        const uint32_t wo = ws_off[kc % 3];

        if (kc + 1 < NCHUNK) CP_WAIT(1);   // group kc done; group kc+1 may still fly
        else                 CP_WAIT(0);   // last chunk: drain all
        __syncthreads();                   // buffer kc visible to all; buffer (kc+2)%3 free
        if (kc + 2 < NCHUNK) {
            cp_async_W(kc + 2, ws_off[(kc + 2) % 3]);
            CP_COMMIT();
        }

        #pragma unroll
        for (int ks = 0; ks < 4; ks++) {
            const int k0 = kc * KC + ks * 16;
            uint32_t a[2][4];
            #pragma unroll
            for (int mt = 0; mt < 2; mt++) {
                const size_t r0o = rb[mt * 2 + 0];
                const size_t r1o = rb[mt * 2 + 1];
                float2 v00 = __ldg(&xg2[(r0o + k0 + cth) >> 1]);
                float2 v10 = __ldg(&xg2[(r1o + k0 + cth) >> 1]);
                float2 v01 = __ldg(&xg2[(r0o + k0 + cth + 8) >> 1]);
                float2 v11 = __ldg(&xg2[(r1o + k0 + cth + 8) >> 1]);
                a[mt][0] = pack_h2(v00.x, v00.y);
                a[mt][1] = pack_h2(v10.x, v10.y);
                a[mt][2] = pack_h2(v01.x, v01.y);
                a[mt][3] = pack_h2(v11.x, v11.y);
            }
            const int br = ks * 16 + (ln & 7) + ((ln >> 3) & 1) * 8;
            #pragma unroll
            for (int ng = 0; ng < 4; ng++) {
                uint32_t bfr[4];
                const int bc = nw * 64 + ng * 16 + (ln >> 4) * 8;
                uint32_t off = (uint32_t)((br * WS_LD + bc) * 2);
                LDSM_X4_T(bfr[0], bfr[1], bfr[2], bfr[3], sb + wo + off);
                #pragma unroll
                for (int mt = 0; mt < 2; mt++) {
                    MMA_F16(c[mt][ng * 2 + 0], a[mt], bfr[0], bfr[1]);
                    MMA_F16(c[mt][ng * 2 + 1], a[mt], bfr[2], bfr[3]);
                }
            }
        }
    }

    // fused epilogue
    float pl[2][2][EDIM];
    #pragma unroll
    for (int mt = 0; mt < 2; mt++)
        #pragma unroll
        for (int h = 0; h < 2; h++)
            #pragma unroll
            for (int e = 0; e < EDIM; e++)
                pl[mt][h][e] = 0.0f;

    #pragma unroll
    for (int nt = 0; nt < 8; nt++)
        #pragma unroll
        for (int i = 0; i < 2; i++) {
            const int cc = nw * 64 + nt * 8 + (ln & 3) * 2 + i;
            const float bb = b1s[cc];
            float w2e[EDIM];
            #pragma unroll
            for (int e = 0; e < EDIM; e++) w2e[e] = w2s[cc * EDIM + e];
            #pragma unroll
            for (int mt = 0; mt < 2; mt++)
                #pragma unroll
                for (int h = 0; h < 2; h++) {
                    float hv = fmaxf(c[mt][nt][h * 2 + i] + bb, 0.0f);
                    #pragma unroll
                    for (int e = 0; e < EDIM; e++)
                        pl[mt][h][e] = fmaf(hv, w2e[e], pl[mt][h][e]);
                }
        }

    #pragma unroll
    for (int off = 1; off < 4; off <<= 1)
        #pragma unroll
        for (int mt = 0; mt < 2; mt++)
            #pragma unroll
            for (int h = 0; h < 2; h++)
                #pragma unroll
                for (int e = 0; e < EDIM; e++)
                    pl[mt][h][e] += __shfl_xor_sync(0xffffffffu, pl[mt][h][e], off);

    if ((ln & 3) == 0) {
        #pragma unroll
        for (int mt = 0; mt < 2; mt++)
            #pragma unroll
            for (int h = 0; h < 2; h++) {
                const int r = mw * 32 + mt * 16 + (ln >> 2) + 8 * h;
                #pragma unroll
                for (int e = 0; e < EDIM; e++)
                    plog[(r * 4 + nw) * EDIM + e] = pl[mt][h][e];
            }
    }
    __syncthreads();

    if (tid < BM) {
        const long long row = row0 + tid;
        float l[EDIM];
        #pragma unroll
        for (int e = 0; e < EDIM; e++) {
            float s = b2s[e];
            #pragma unroll
            for (int w = 0; w < 4; w++) s += plog[(tid * 4 + w) * EDIM + e];
            l[e] = s;
        }
        int i1 = 0;
        #pragma unroll
        for (int e = 1; e < EDIM; e++) if (l[e] > l[i1]) i1 = e;
        int i2 = (i1 == 0) ? 1 : 0;
        #pragma unroll
        for (int e = 0; e < EDIM; e++) if (e != i1 && l[e] > l[i2]) i2 = e;
        float m3 = -3.4e38f;
        #pragma unroll
        for (int e = 0; e < EDIM; e++) if (e != i1 && e != i2 && l[e] > m3) m3 = l[e];

        float e2  = __expf(l[i2] - l[i1]);
        float inv = 1.0f / (1.0f + e2);
        #pragma unroll
        for (int e = 0; e < EDIM; e++)
            out_gates[row * EDIM + e] = (e == i1) ? inv : ((e == i2) ? e2 * inv : 0.0f);
        if (write_idx) {
            out_idx[row * 2 + 0] = (float)i1;
            out_idx[row * 2 + 1] = (float)i2;
        }
        if ((l[i1] - l[i2] < TAU) || (l[i2] - m3 < TAU)) {
            int pos = atomicAdd(&g_count, 1);
            if (pos < FIXCAP) g_rows[pos] = (int)row;
        }
    }
}

// ===================== kernel 2: batched exact fp32 fixup (MLP-8) =====================
__global__ __launch_bounds__(256)
void fixup_kernel(const float* __restrict__ x,
                  const float* __restrict__ W1,
                  const float* __restrict__ b1,
                  const float* __restrict__ W2,
                  const float* __restrict__ b2,
                  float* __restrict__ out_gates,
                  float* __restrict__ out_idx,
                  int write_idx)
{
    int cnt = g_count; if (cnt > FIXCAP) cnt = FIXCAP;
    const int base = blockIdx.x * RPF;
    if (base >= cnt) return;
    const int nr = min(RPF, cnt - base);
    const int tid = threadIdx.x;
    const int wrp = tid >> 5, ln = tid & 31;

    __shared__ float xs[RPF][DDIM];
    __shared__ float hs[RPF][DDIM];

    for (int r = 0; r < nr; r++)
        xs[r][tid] = x[(long long)g_rows[base + r] * DDIM + tid];
    for (int r = nr; r < RPF; r++)
        xs[r][tid] = 0.0f;
    __syncthreads();

    float acc[RPF];
    #pragma unroll
    for (int r = 0; r < RPF; r++) acc[r] = 0.0f;

    #pragma unroll 2
    for (int k0 = 0; k0 < DDIM; k0 += 8) {
        float w[8];
        #pragma unroll
        for (int u = 0; u < 8; u++)
            w[u] = __ldg(&W1[(k0 + u) * HDIM + tid]);
        #pragma unroll
        for (int u = 0; u < 8; u++)
            #pragma unroll
            for (int r = 0; r < RPF; r++)
                acc[r] = fmaf(xs[r][k0 + u], w[u], acc[r]);
    }

    const float bb1 = b1[tid];
    #pragma unroll
    for (int r = 0; r < RPF; r++)
        hs[r][tid] = fmaxf(acc[r] + bb1, 0.0f);
    __syncthreads();

    for (int r = wrp; r < nr; r += 8) {
        float pl[EDIM] = {0.f, 0.f, 0.f, 0.f, 0.f};
        #pragma unroll
        for (int j = 0; j < 8; j++) {
            int n = ln * 8 + j;
            float hv = hs[r][n];
            #pragma unroll
            for (int e = 0; e < EDIM; e++)
                pl[e] = fmaf(hv, W2[n * EDIM + e], pl[e]);
        }
        #pragma unroll
        for (int off = 16; off > 0; off >>= 1)
            #pragma unroll
            for (int e = 0; e < EDIM; e++)
                pl[e] += __shfl_xor_sync(0xffffffffu, pl[e], off);

        if (ln == 0) {
            const long long row = g_rows[base + r];
            float l[EDIM];
            #pragma unroll
            for (int e = 0; e < EDIM; e++) l[e] = pl[e] + b2[e];
            int i1 = 0;
            #pragma unroll
            for (int e = 1; e < EDIM; e++) if (l[e] > l[i1]) i1 = e;
            int i2 = (i1 == 0) ? 1 : 0;
            #pragma unroll
            for (int e = 0; e < EDIM; e++) if (e != i1 && l[e] > l[i2]) i2 = e;
            float e2  = __expf(l[i2] - l[i1]);
            float inv = 1.0f / (1.0f + e2);
            #pragma unroll
            for (int e = 0; e < EDIM; e++)
                out_gates[row * EDIM + e] = (e == i1) ? inv : ((e == i2) ? e2 * inv : 0.0f);
            if (write_idx) {
                out_idx[row * 2 + 0] = (float)i1;
                out_idx[row * 2 + 1] = (float)i2;
            }
        }
    }
}

// ===================== launcher =====================
extern "C" void kernel_launch(void* const* d_in, const int* in_sizes, int n_in,
                              void* d_out, int out_size)
{
    const float* x  = (const float*)d_in[0];
    const float* W1 = (const float*)d_in[1];
    const float* b1 = (const float*)d_in[2];
    const float* W2 = (const float*)d_in[3];
    const float* b2 = (const float*)d_in[4];

    const long long Brows = (long long)in_sizes[0] / DDIM;
    float* gates = (float*)d_out;
    float* idxf  = gates + Brows * EDIM;
    int write_idx = ((long long)out_size >= Brows * (EDIM + 2)) ? 1 : 0;

    cudaFuncSetAttribute(gating_mma_kernel,
                         cudaFuncAttributeMaxDynamicSharedMemorySize, SMEM_TOTAL);

    prep_kernel<<<(DDIM * HDIM) / 256, 256>>>(W1);
    gating_mma_kernel<<<(unsigned)(Brows / BM), 256, SMEM_TOTAL>>>(
        x, b1, W2, b2, gates, idxf, write_idx);
    fixup_kernel<<<FIXCAP / RPF, 256>>>(x, W1, b1, W2, b2, gates, idxf, write_idx);
}

// round 14
// speedup vs baseline: 1.2091x; 1.2091x over previous
#include <cuda_runtime.h>
#include <cuda_fp16.h>
#include <cstdint>

// ===================== problem constants =====================
#define DDIM 256
#define HDIM 256
#define EDIM 5
#define BM   64            // rows per MMA CTA
#define KC   32
#define NCHUNK (DDIM / KC) // 8
#define TAU  3e-3f
#define FIXCAP 16384
#define RPF  16

// W smem leading dim (fp16), padded for conflict-free ldmatrix
#define WS_LD 264
#define WBUF_BYTES (KC * WS_LD * 2)   // 16896

// dynamic smem byte offsets (MMA kernel) — 3 W buffers + tables
#define WS0_OFF   0
#define WS1_OFF   16896
#define WS2_OFF   33792
#define PLOG_OFF  50688    // float[64][4][5] = 5120
#define B1_OFF    55808    // 1024
#define W2_OFF    56832    // 5120
#define B2_OFF    61952    // 64
#define SMEM_TOTAL 62016   // x2 CTAs = 124032 <= 228KB -> occupancy 2 preserved

// ===================== device scratch =====================
__device__ int    g_count;
__device__ int    g_rows[FIXCAP];
__device__ __half g_w1h[DDIM * HDIM];

// ===================== PTX helpers =====================
__device__ __forceinline__ uint32_t smem_u32(const void* p) {
    uint32_t a;
    asm("{ .reg .u64 t; cvta.to.shared.u64 t, %1; cvt.u32.u64 %0, t; }" : "=r"(a) : "l"(p));
    return a;
}

#define LDSM_X4_T(r0, r1, r2, r3, addr)                                            \
    asm volatile("ldmatrix.sync.aligned.m8n8.x4.trans.shared.b16 {%0,%1,%2,%3}, [%4];" \
        : "=r"(r0), "=r"(r1), "=r"(r2), "=r"(r3) : "r"(addr))

#define MMA_F16(d, a, b0, b1)                                                      \
    asm volatile("mma.sync.aligned.m16n8k16.row.col.f32.f16.f16.f32 "              \
        "{%0,%1,%2,%3}, {%4,%5,%6,%7}, {%8,%9}, {%0,%1,%2,%3};"                    \
        : "+f"((d)[0]), "+f"((d)[1]), "+f"((d)[2]), "+f"((d)[3])                   \
        : "r"((a)[0]), "r"((a)[1]), "r"((a)[2]), "r"((a)[3]), "r"(b0), "r"(b1))

#define CP_ASYNC16(dst, src)                                                       \
    asm volatile("cp.async.cg.shared.global [%0], [%1], 16;" :: "r"(dst), "l"(src))
#define CP_COMMIT() asm volatile("cp.async.commit_group;" ::: "memory")
#define CP_WAIT(n)  asm volatile("cp.async.wait_group %0;" :: "n"(n) : "memory")

__device__ __forceinline__ uint32_t pack_h2(float a, float b) {
    __half2 v = __floats2half2_rn(a, b);
    return *reinterpret_cast<uint32_t*>(&v);
}

// ===================== kernel 0: prep =====================
__global__ __launch_bounds__(256)
void prep_kernel(const float* __restrict__ W1) {
    int i = blockIdx.x * 256 + threadIdx.x;
    g_w1h[i] = __float2half(W1[i]);
    if (i == 0) g_count = 0;
}

// ===================== kernel 1: MMA kernel (R12 + 3-stage W pipeline) =====================
__global__ __launch_bounds__(256, 2)
void gating_mma_kernel(const float* __restrict__ x,
                       const float* __restrict__ b1,
                       const float* __restrict__ W2,
                       const float* __restrict__ b2,
                       float* __restrict__ out_gates,
                       float* __restrict__ out_idx,
                       int write_idx)
{
    extern __shared__ __align__(128) char smem[];
    const uint32_t sb = smem_u32(smem);
    const int tid  = threadIdx.x;
    const int wrp  = tid >> 5;
    const int ln   = tid & 31;
    const int mw   = wrp >> 2;
    const int nw   = wrp & 3;
    const long long row0 = (long long)blockIdx.x * BM;

    float* plog = (float*)(smem + PLOG_OFF);
    float* b1s  = (float*)(smem + B1_OFF);
    float* w2s  = (float*)(smem + W2_OFF);
    float* b2s  = (float*)(smem + B2_OFF);

    b1s[tid] = b1[tid];
    if (tid < EDIM) b2s[tid] = b2[tid];
    #pragma unroll
    for (int i = 0; i < 5; i++) {
        int v = tid + i * 256;
        if (v < HDIM * EDIM) w2s[v] = W2[v];
    }

    const float2* xg2 = (const float2*)x;
    size_t rb[4];
    #pragma unroll
    for (int i = 0; i < 4; i++)
        rb[i] = (size_t)(row0 + mw * 32 + (ln >> 2) + 8 * i) * DDIM;
    const int cth = (ln & 3) * 2;

    const uint32_t ws_off[3] = {WS0_OFF, WS1_OFF, WS2_OFF};

    auto cp_async_W = [&](int chunk, uint32_t off) {
        const __half* src_base = g_w1h + (size_t)(chunk * KC) * HDIM;
        #pragma unroll
        for (int t = 0; t < 4; t++) {
            int v   = tid + t * 256;
            int r   = v >> 5;
            int g   = v & 31;
            uint32_t dst = sb + off + (uint32_t)(r * (WS_LD * 2) + g * 16);
            CP_ASYNC16(dst, src_base + r * HDIM + g * 8);
        }
    };

    float c[2][8][4];
    #pragma unroll
    for (int mt = 0; mt < 2; mt++)
        #pragma unroll
        for (int nt = 0; nt < 8; nt++)
            #pragma unroll
            for (int r = 0; r < 4; r++)
                c[mt][nt][r] = 0.0f;

    // prologue: 2 chunks in flight
    cp_async_W(0, ws_off[0]); CP_COMMIT();
    cp_async_W(1, ws_off[1]); CP_COMMIT();

    #pragma unroll
    for (int kc = 0; kc < NCHUNK; kc++) {
        const uint32_t wo = ws_off[kc % 3];

        if (kc + 1 < NCHUNK) CP_WAIT(1);   // group kc resident; group kc+1 may still fly
        else                 CP_WAIT(0);
        __syncthreads();                   // buffer kc visible; buffer (kc+2)%3 free
        if (kc + 2 < NCHUNK) {
            cp_async_W(kc + 2, ws_off[(kc + 2) % 3]);
            CP_COMMIT();
        }

        #pragma unroll
        for (int ks = 0; ks < 2; ks++) {
            const int k0 = kc * KC + ks * 16;
            uint32_t a[2][4];
            #pragma unroll
            for (int mt = 0; mt < 2; mt++) {
                const size_t r0o = rb[mt * 2 + 0];
                const size_t r1o = rb[mt * 2 + 1];
                float2 v00 = __ldg(&xg2[(r0o + k0 + cth) >> 1]);
                float2 v10 = __ldg(&xg2[(r1o + k0 + cth) >> 1]);
                float2 v01 = __ldg(&xg2[(r0o + k0 + cth + 8) >> 1]);
                float2 v11 = __ldg(&xg2[(r1o + k0 + cth + 8) >> 1]);
                a[mt][0] = pack_h2(v00.x, v00.y);
                a[mt][1] = pack_h2(v10.x, v10.y);
                a[mt][2] = pack_h2(v01.x, v01.y);
                a[mt][3] = pack_h2(v11.x, v11.y);
            }
            const int br = ks * 16 + (ln & 7) + ((ln >> 3) & 1) * 8;
            #pragma unroll
            for (int ng = 0; ng < 4; ng++) {
                uint32_t bfr[4];
                const int bc = nw * 64 + ng * 16 + (ln >> 4) * 8;
                uint32_t off = (uint32_t)((br * WS_LD + bc) * 2);
                LDSM_X4_T(bfr[0], bfr[1], bfr[2], bfr[3], sb + wo + off);
                #pragma unroll
                for (int mt = 0; mt < 2; mt++) {
                    MMA_F16(c[mt][ng * 2 + 0], a[mt], bfr[0], bfr[1]);
                    MMA_F16(c[mt][ng * 2 + 1], a[mt], bfr[2], bfr[3]);
                }
            }
        }
    }

    // fused epilogue
    float pl[2][2][EDIM];
    #pragma unroll
    for (int mt = 0; mt < 2; mt++)
        #pragma unroll
        for (int h = 0; h < 2; h++)
            #pragma unroll
            for (int e = 0; e < EDIM; e++)
                pl[mt][h][e] = 0.0f;

    #pragma unroll
    for (int nt = 0; nt < 8; nt++)
        #pragma unroll
        for (int i = 0; i < 2; i++) {
            const int cc = nw * 64 + nt * 8 + (ln & 3) * 2 + i;
            const float bb = b1s[cc];
            float w2e[EDIM];
            #pragma unroll
            for (int e = 0; e < EDIM; e++) w2e[e] = w2s[cc * EDIM + e];
            #pragma unroll
            for (int mt = 0; mt < 2; mt++)
                #pragma unroll
                for (int h = 0; h < 2; h++) {
                    float hv = fmaxf(c[mt][nt][h * 2 + i] + bb, 0.0f);
                    #pragma unroll
                    for (int e = 0; e < EDIM; e++)
                        pl[mt][h][e] = fmaf(hv, w2e[e], pl[mt][h][e]);
                }
        }

    #pragma unroll
    for (int off = 1; off < 4; off <<= 1)
        #pragma unroll
        for (int mt = 0; mt < 2; mt++)
            #pragma unroll
            for (int h = 0; h < 2; h++)
                #pragma unroll
                for (int e = 0; e < EDIM; e++)
                    pl[mt][h][e] += __shfl_xor_sync(0xffffffffu, pl[mt][h][e], off);

    if ((ln & 3) == 0) {
        #pragma unroll
        for (int mt = 0; mt < 2; mt++)
            #pragma unroll
            for (int h = 0; h < 2; h++) {
                const int r = mw * 32 + mt * 16 + (ln >> 2) + 8 * h;
                #pragma unroll
                for (int e = 0; e < EDIM; e++)
                    plog[(r * 4 + nw) * EDIM + e] = pl[mt][h][e];
            }
    }
    __syncthreads();

    if (tid < BM) {
        const long long row = row0 + tid;
        float l[EDIM];
        #pragma unroll
        for (int e = 0; e < EDIM; e++) {
            float s = b2s[e];
            #pragma unroll
            for (int w = 0; w < 4; w++) s += plog[(tid * 4 + w) * EDIM + e];
            l[e] = s;
        }
        int i1 = 0;
        #pragma unroll
        for (int e = 1; e < EDIM; e++) if (l[e] > l[i1]) i1 = e;
        int i2 = (i1 == 0) ? 1 : 0;
        #pragma unroll
        for (int e = 0; e < EDIM; e++) if (e != i1 && l[e] > l[i2]) i2 = e;
        float m3 = -3.4e38f;
        #pragma unroll
        for (int e = 0; e < EDIM; e++) if (e != i1 && e != i2 && l[e] > m3) m3 = l[e];

        float e2  = __expf(l[i2] - l[i1]);
        float inv = 1.0f / (1.0f + e2);
        #pragma unroll
        for (int e = 0; e < EDIM; e++)
            out_gates[row * EDIM + e] = (e == i1) ? inv : ((e == i2) ? e2 * inv : 0.0f);
        if (write_idx) {
            out_idx[row * 2 + 0] = (float)i1;
            out_idx[row * 2 + 1] = (float)i2;
        }
        if ((l[i1] - l[i2] < TAU) || (l[i2] - m3 < TAU)) {
            int pos = atomicAdd(&g_count, 1);
            if (pos < FIXCAP) g_rows[pos] = (int)row;
        }
    }
}

// ===================== kernel 2: batched exact fp32 fixup (MLP-8) =====================
__global__ __launch_bounds__(256)
void fixup_kernel(const float* __restrict__ x,
                  const float* __restrict__ W1,
                  const float* __restrict__ b1,
                  const float* __restrict__ W2,
                  const float* __restrict__ b2,
                  float* __restrict__ out_gates,
                  float* __restrict__ out_idx,
                  int write_idx)
{
    int cnt = g_count; if (cnt > FIXCAP) cnt = FIXCAP;
    const int base = blockIdx.x * RPF;
    if (base >= cnt) return;
    const int nr = min(RPF, cnt - base);
    const int tid = threadIdx.x;
    const int wrp = tid >> 5, ln = tid & 31;

    __shared__ float xs[RPF][DDIM];
    __shared__ float hs[RPF][DDIM];

    for (int r = 0; r < nr; r++)
        xs[r][tid] = x[(long long)g_rows[base + r] * DDIM + tid];
    for (int r = nr; r < RPF; r++)
        xs[r][tid] = 0.0f;
    __syncthreads();

    float acc[RPF];
    #pragma unroll
    for (int r = 0; r < RPF; r++) acc[r] = 0.0f;

    #pragma unroll 2
    for (int k0 = 0; k0 < DDIM; k0 += 8) {
        float w[8];
        #pragma unroll
        for (int u = 0; u < 8; u++)
            w[u] = __ldg(&W1[(k0 + u) * HDIM + tid]);
        #pragma unroll
        for (int u = 0; u < 8; u++)
            #pragma unroll
            for (int r = 0; r < RPF; r++)
                acc[r] = fmaf(xs[r][k0 + u], w[u], acc[r]);
    }

    const float bb1 = b1[tid];
    #pragma unroll
    for (int r = 0; r < RPF; r++)
        hs[r][tid] = fmaxf(acc[r] + bb1, 0.0f);
    __syncthreads();

    for (int r = wrp; r < nr; r += 8) {
        float pl[EDIM] = {0.f, 0.f, 0.f, 0.f, 0.f};
        #pragma unroll
        for (int j = 0; j < 8; j++) {
            int n = ln * 8 + j;
            float hv = hs[r][n];
            #pragma unroll
            for (int e = 0; e < EDIM; e++)
                pl[e] = fmaf(hv, W2[n * EDIM + e], pl[e]);
        }
        #pragma unroll
        for (int off = 16; off > 0; off >>= 1)
            #pragma unroll
            for (int e = 0; e < EDIM; e++)
                pl[e] += __shfl_xor_sync(0xffffffffu, pl[e], off);

        if (ln == 0) {
            const long long row = g_rows[base + r];
            float l[EDIM];
            #pragma unroll
            for (int e = 0; e < EDIM; e++) l[e] = pl[e] + b2[e];
            int i1 = 0;
            #pragma unroll
            for (int e = 1; e < EDIM; e++) if (l[e] > l[i1]) i1 = e;
            int i2 = (i1 == 0) ? 1 : 0;
            #pragma unroll
            for (int e = 0; e < EDIM; e++) if (e != i1 && l[e] > l[i2]) i2 = e;
            float e2  = __expf(l[i2] - l[i1]);
            float inv = 1.0f / (1.0f + e2);
            #pragma unroll
            for (int e = 0; e < EDIM; e++)
                out_gates[row * EDIM + e] = (e == i1) ? inv : ((e == i2) ? e2 * inv : 0.0f);
            if (write_idx) {
                out_idx[row * 2 + 0] = (float)i1;
                out_idx[row * 2 + 1] = (float)i2;
            }
        }
    }
}

// ===================== launcher =====================
extern "C" void kernel_launch(void* const* d_in, const int* in_sizes, int n_in,
                              void* d_out, int out_size)
{
    const float* x  = (const float*)d_in[0];
    const float* W1 = (const float*)d_in[1];
    const float* b1 = (const float*)d_in[2];
    const float* W2 = (const float*)d_in[3];
    const float* b2 = (const float*)d_in[4];

    const long long Brows = (long long)in_sizes[0] / DDIM;
    float* gates = (float*)d_out;
    float* idxf  = gates + Brows * EDIM;
    int write_idx = ((long long)out_size >= Brows * (EDIM + 2)) ? 1 : 0;

    cudaFuncSetAttribute(gating_mma_kernel,
                         cudaFuncAttributeMaxDynamicSharedMemorySize, SMEM_TOTAL);

    prep_kernel<<<(DDIM * HDIM) / 256, 256>>>(W1);
    gating_mma_kernel<<<(unsigned)(Brows / BM), 256, SMEM_TOTAL>>>(
        x, b1, W2, b2, gates, idxf, write_idx);
    fixup_kernel<<<FIXCAP / RPF, 256>>>(x, W1, b1, W2, b2, gates, idxf, write_idx);
}